// round 13
// baseline (speedup 1.0000x reference)
#include <cuda_runtime.h>
#include <cuda_fp16.h>
#include <cstdint>

#define NROWS 16384
#define KDIM  16384
#define NCOLS 64
#define KC    64
#define NCHUNK (KDIM / KC)
#define BSTRIDE ((KC * 2) / 16)   // uint4s per chunk of one B row = 8

// -------- device scratch --------
__device__ __align__(256) float  g_sup[(size_t)NROWS * NCOLS];
__device__ __align__(256) __half g_bh[(size_t)NCOLS * KDIM];   // support^T (fp16)

// -------- helpers --------
__device__ __forceinline__ uint32_t smem_u32(const void* p) {
    uint32_t a;
    asm("{ .reg .u64 t; cvta.to.shared.u64 t, %1; cvt.u32.u64 %0, t; }" : "=r"(a) : "l"(p));
    return a;
}
__device__ __forceinline__ uint32_t sw128(uint32_t off) { return off ^ ((off >> 3) & 0x70); }

__device__ __forceinline__ uint32_t pack2h(float a, float b) {   // a -> LOW half
    uint32_t r;
    asm("cvt.rn.f16x2.f32 %0, %1, %2;" : "=r"(r) : "f"(b), "f"(a));
    return r;
}
__device__ __forceinline__ void sts128(uint32_t addr, uint32_t a, uint32_t b, uint32_t c, uint32_t d) {
    asm volatile("st.shared.v4.b32 [%0], {%1,%2,%3,%4};"
                 :: "r"(addr), "r"(a), "r"(b), "r"(c), "r"(d) : "memory");
}
__device__ __forceinline__ void lds128f(uint32_t addr, float* v) {
    asm volatile("ld.shared.v4.f32 {%0,%1,%2,%3}, [%4];"
                 : "=f"(v[0]), "=f"(v[1]), "=f"(v[2]), "=f"(v[3]) : "r"(addr));
}
__device__ __forceinline__ void cp_async16(uint32_t saddr, const void* gaddr) {
    asm volatile("cp.async.cg.shared.global [%0], [%1], 16;"
                 :: "r"(saddr), "l"(gaddr) : "memory");
}
#define CP_COMMIT() asm volatile("cp.async.commit_group;" ::: "memory")
#define CP_WAIT0()  asm volatile("cp.async.wait_group 0;" ::: "memory")

#define LDSM4(r, addr) \
    asm volatile("ldmatrix.sync.aligned.m8n8.x4.shared.b16 {%0,%1,%2,%3}, [%4];" \
                 : "=r"((r)[0]), "=r"((r)[1]), "=r"((r)[2]), "=r"((r)[3]) : "r"(addr))

#define MMAH(d, a, b0_, b1_) \
    asm volatile("mma.sync.aligned.m16n8k16.row.col.f32.f16.f16.f32 " \
                 "{%0,%1,%2,%3}, {%4,%5,%6,%7}, {%8,%9}, {%0,%1,%2,%3};" \
                 : "+f"((d)[0]), "+f"((d)[1]), "+f"((d)[2]), "+f"((d)[3]) \
                 : "r"((a)[0]), "r"((a)[1]), "r"((a)[2]), "r"((a)[3]), \
                   "r"(b0_), "r"(b1_))

// -------- prep: support = x @ W ; store fp32 + fp16 transposed plane --------
__global__ __launch_bounds__(256) void gcn_prep(const float* __restrict__ x,
                                                const float* __restrict__ W) {
    int tid = threadIdx.x;
    int rg = tid >> 3, cg = tid & 7;
    int row0 = blockIdx.x * 128 + rg * 4;   // k dim of support^T
    int c0 = cg * 8;                        // n dim
    float acc[4][8];
#pragma unroll
    for (int i = 0; i < 4; i++)
#pragma unroll
        for (int j = 0; j < 8; j++) acc[i][j] = 0.f;

    const float4* x4 = reinterpret_cast<const float4*>(x);
    const float4* W4 = reinterpret_cast<const float4*>(W);

    for (int k4 = 0; k4 < 64; k4++) {
        float4 xv[4];
#pragma unroll
        for (int i = 0; i < 4; i++) xv[i] = __ldg(&x4[(size_t)(row0 + i) * 64 + k4]);
#pragma unroll
        for (int j = 0; j < 4; j++) {
            float4 wa = __ldg(&W4[(k4 * 4 + j) * 16 + cg * 2]);
            float4 wb = __ldg(&W4[(k4 * 4 + j) * 16 + cg * 2 + 1]);
#pragma unroll
            for (int i = 0; i < 4; i++) {
                float xs = (j == 0) ? xv[i].x : (j == 1) ? xv[i].y : (j == 2) ? xv[i].z : xv[i].w;
                acc[i][0] = fmaf(xs, wa.x, acc[i][0]);
                acc[i][1] = fmaf(xs, wa.y, acc[i][1]);
                acc[i][2] = fmaf(xs, wa.z, acc[i][2]);
                acc[i][3] = fmaf(xs, wa.w, acc[i][3]);
                acc[i][4] = fmaf(xs, wb.x, acc[i][4]);
                acc[i][5] = fmaf(xs, wb.y, acc[i][5]);
                acc[i][6] = fmaf(xs, wb.z, acc[i][6]);
                acc[i][7] = fmaf(xs, wb.w, acc[i][7]);
            }
        }
    }
#pragma unroll
    for (int i = 0; i < 4; i++) {
        float* sp = g_sup + (size_t)(row0 + i) * NCOLS + c0;
        reinterpret_cast<float4*>(sp)[0] = make_float4(acc[i][0], acc[i][1], acc[i][2], acc[i][3]);
        reinterpret_cast<float4*>(sp)[1] = make_float4(acc[i][4], acc[i][5], acc[i][6], acc[i][7]);
    }
#pragma unroll
    for (int j = 0; j < 8; j++) {
        int n = c0 + j;
        uint32_t hv0 = pack2h(acc[0][j], acc[1][j]);
        uint32_t hv1 = pack2h(acc[2][j], acc[3][j]);
        *reinterpret_cast<uint2*>(g_bh + (size_t)n * KDIM + row0) = make_uint2(hv0, hv1);
    }
}

// -------- main: out = relu(adj @ support + support + b) --------
// 256 CTAs x 64 rows, 256 threads, 2 CTAs/SM. Warp grid 2m x 2n x 2k; tile 32x32 on K/2.
// Stage: A 64x128B fp16 = 8KB | B 8KB. A: reg ring distance 2. B: cp.async.cg.
#define STAGE_BYTES 16384
#define SMEM_MAIN   (1024 + 2 * STAGE_BYTES)

__device__ __forceinline__ void stage_A(uint32_t At, const float* f,
                                        uint32_t s0, uint32_t s1) {
    uint32_t h[8];
#pragma unroll
    for (int q = 0; q < 8; q++) h[q] = pack2h(f[2 * q], f[2 * q + 1]);
    sts128(At + s0, h[0], h[1], h[2], h[3]);
    sts128(At + s1, h[4], h[5], h[6], h[7]);
}

__global__ __launch_bounds__(256, 2) void gcn_main(const float* __restrict__ adj,
                                                   const float* __restrict__ bias,
                                                   float* __restrict__ out) {
    extern __shared__ char dsm[];
    uint32_t tiles = (smem_u32(dsm) + 1023) & ~1023u;
    int tid = threadIdx.x;
    int wid = tid >> 5;
    int lane = tid & 31;
    int row0 = blockIdx.x * 64;
    int wm = wid & 1, wn = (wid >> 1) & 1, wk = wid >> 2;

    // A loader: 64 rows x 4 segs of 16 floats -> 32B fp16
    int arow = tid >> 2, aseg = tid & 3;
    uint32_t a_s0 = sw128((uint32_t)arow * 128 + (uint32_t)aseg * 32);
    uint32_t a_s1 = sw128((uint32_t)arow * 128 + (uint32_t)aseg * 32 + 16);
    const float4* apbase = reinterpret_cast<const float4*>(
        adj + (size_t)(row0 + arow) * KDIM + aseg * 16);

    // B loader: 64 rows x 4 segs of 32B via cp.async (2x16B per thread)
    int bn = tid >> 2, bq = tid & 3;
    const uint4* bpbase = reinterpret_cast<const uint4*>(
        reinterpret_cast<const char*>(g_bh) + ((size_t)bn * KDIM) * 2 + (size_t)bq * 32);
    uint32_t b_s0 = sw128((uint32_t)bn * 128 + (uint32_t)bq * 32);
    uint32_t b_s1 = sw128((uint32_t)bn * 128 + (uint32_t)bq * 32 + 16);

#define CP_B(St, c) do { \
    const uint4* _s = bpbase + (size_t)(c) * BSTRIDE; \
    cp_async16((St) + 8192 + b_s0, _s); \
    cp_async16((St) + 8192 + b_s1, _s + 1); \
    CP_COMMIT(); \
} while (0)

    // fragment lane mappings
    uint32_t a_r = ((lane >> 3) & 1) * 8 + (lane & 7);
    uint32_t a_k = ((lane >> 4) & 1) * 16;
    uint32_t b_n = ((lane >> 4) & 1) * 8 + (lane & 7);
    uint32_t b_k = ((lane >> 3) & 1) * 16;
    uint32_t arowb[2], browb[2];
#pragma unroll
    for (int mt = 0; mt < 2; mt++) arowb[mt] = (wm * 32 + mt * 16 + a_r) * 128;
#pragma unroll
    for (int p = 0; p < 2; p++)   browb[p]  = (wn * 32 + p * 16 + b_n) * 128;

    float acc[2][4][4];
#pragma unroll
    for (int mt = 0; mt < 2; mt++)
#pragma unroll
        for (int nt = 0; nt < 4; nt++)
#pragma unroll
            for (int j = 0; j < 4; j++) acc[mt][nt][j] = 0.f;

    uint32_t St0 = tiles, St1 = tiles + STAGE_BYTES;

#define MMA_CHUNK(At, Bt) do { \
    _Pragma("unroll") \
    for (int ks = 0; ks < 2; ks++) { \
        uint32_t ko = (uint32_t)wk * 64 + (uint32_t)(ks * 32); \
        uint32_t af[2][4], bf[2][4]; \
        _Pragma("unroll") \
        for (int mt = 0; mt < 2; mt++) \
            LDSM4(af[mt], (At) + sw128(arowb[mt] + ko + a_k)); \
        _Pragma("unroll") \
        for (int p = 0; p < 2; p++) \
            LDSM4(bf[p], (Bt) + sw128(browb[p] + ko + b_k)); \
        _Pragma("unroll") \
        for (int mt = 0; mt < 2; mt++) { \
            _Pragma("unroll") \
            for (int nt = 0; nt < 4; nt++) { \
                int p = nt >> 1, h = (nt & 1) * 2; \
                MMAH(acc[mt][nt], af[mt], bf[p][h], bf[p][h + 1]); \
            } \
        } \
    } \
} while (0)

    float av0[16], av1[16];

    // ---- prologue: chunk 0 staged into St0; chunk 1 A-regs in flight ----
    {
        CP_B(St0, 0);
#pragma unroll
        for (int q = 0; q < 4; q++)
            reinterpret_cast<float4*>(av0)[q] = __ldcs(&apbase[q]);
        stage_A(St0, av0, a_s0, a_s1);
#pragma unroll
        for (int q = 0; q < 4; q++)
            reinterpret_cast<float4*>(av1)[q] = __ldcs(&apbase[(size_t)(KC / 4) + q]);
        CP_WAIT0();
    }
    __syncthreads();

    // ---- main loop (unrolled x2; A distance-2 reg ring, B cp.async into free stage) ----
#pragma unroll 1
    for (int c = 0; c < NCHUNK; c += 2) {
        // chunk c on St0; B(c+1) -> St1 async; A(c+2) -> regs; stage A(c+1) -> St1
        CP_B(St1, c + 1);
        if (c + 2 < NCHUNK) {
            const float4* ap = apbase + (size_t)(c + 2) * (KC / 4);
#pragma unroll
            for (int q = 0; q < 4; q++)
                reinterpret_cast<float4*>(av0)[q] = __ldcs(&ap[q]);
        }
        MMA_CHUNK(St0, St0 + 8192);
        stage_A(St1, av1, a_s0, a_s1);
        CP_WAIT0();
        __syncthreads();

        // chunk c+1 on St1; B(c+2) -> St0 async; A(c+3) -> regs; stage A(c+2) -> St0
        bool more = (c + 2 < NCHUNK);
        if (more) CP_B(St0, c + 2);
        if (c + 3 < NCHUNK) {
            const float4* ap = apbase + (size_t)(c + 3) * (KC / 4);
#pragma unroll
            for (int q = 0; q < 4; q++)
                reinterpret_cast<float4*>(av1)[q] = __ldcs(&ap[q]);
        }
        MMA_CHUNK(St1, St1 + 8192);
        if (more) stage_A(St0, av0, a_s0, a_s1);
        CP_WAIT0();
        __syncthreads();
    }
#undef MMA_CHUNK
#undef CP_B

    // ---- merge k-split partials: wk=1 warps dump accs to smem ----
    if (wk == 1) {
#pragma unroll
        for (int mt = 0; mt < 2; mt++)
#pragma unroll
            for (int nt = 0; nt < 4; nt++) {
                uint32_t off = tiles + (uint32_t)(wid & 3) * 4096 +
                               (uint32_t)(mt * 4 + nt) * 512 + (uint32_t)lane * 16;
                sts128(off, __float_as_uint(acc[mt][nt][0]), __float_as_uint(acc[mt][nt][1]),
                             __float_as_uint(acc[mt][nt][2]), __float_as_uint(acc[mt][nt][3]));
            }
    }
    __syncthreads();

    // ---- epilogue (wk=0 warps): out = relu(acc + partial + support + bias) ----
    if (wk == 0) {
        int g = lane >> 2, t = lane & 3;
#pragma unroll
        for (int mt = 0; mt < 2; mt++) {
            int ra = row0 + wm * 32 + mt * 16 + g;
#pragma unroll
            for (int nt = 0; nt < 4; nt++) {
                float p[4];
                lds128f(tiles + (uint32_t)wid * 4096 + (uint32_t)(mt * 4 + nt) * 512 +
                        (uint32_t)lane * 16, p);
                int col = wn * 32 + nt * 8 + t * 2;
                float2 bb = *reinterpret_cast<const float2*>(bias + col);
                float2 s0 = *reinterpret_cast<const float2*>(g_sup + (size_t)ra * NCOLS + col);
                float2 s1 = *reinterpret_cast<const float2*>(g_sup + (size_t)(ra + 8) * NCOLS + col);
                float2 r0, r1;
                r0.x = fmaxf(acc[mt][nt][0] + p[0] + s0.x + bb.x, 0.f);
                r0.y = fmaxf(acc[mt][nt][1] + p[1] + s0.y + bb.y, 0.f);
                r1.x = fmaxf(acc[mt][nt][2] + p[2] + s1.x + bb.x, 0.f);
                r1.y = fmaxf(acc[mt][nt][3] + p[3] + s1.y + bb.y, 0.f);
                *reinterpret_cast<float2*>(out + (size_t)ra * NCOLS + col) = r0;
                *reinterpret_cast<float2*>(out + (size_t)(ra + 8) * NCOLS + col) = r1;
            }
        }
    }
}

extern "C" void kernel_launch(void* const* d_in, const int* in_sizes, int n_in,
                              void* d_out, int out_size) {
    const float *x = nullptr, *adj = nullptr, *W = nullptr, *b = nullptr;
    for (int i = 0; i < n_in; i++) {
        long s = in_sizes[i];
        if (s == (long)NROWS * 256)        x   = (const float*)d_in[i];
        else if (s == (long)NROWS * NROWS) adj = (const float*)d_in[i];
        else if (s == 256L * NCOLS)        W   = (const float*)d_in[i];
        else if (s == (long)NCOLS)         b   = (const float*)d_in[i];
    }
    cudaFuncSetAttribute(gcn_main, cudaFuncAttributeMaxDynamicSharedMemorySize, SMEM_MAIN);
    gcn_prep<<<128, 256>>>(x, W);
    gcn_main<<<256, 256, SMEM_MAIN>>>(adj, b, (float*)d_out);
}

// round 14
// speedup vs baseline: 1.1311x; 1.1311x over previous
#include <cuda_runtime.h>
#include <cuda_fp16.h>
#include <cstdint>

#define NROWS 16384
#define KDIM  16384
#define NCOLS 64
#define KC    64
#define NCHUNK (KDIM / KC)
#define BSTRIDE ((KC * 2) / 16)   // uint4s per chunk of one B row = 8

// -------- device scratch --------
__device__ __align__(256) float  g_sup[(size_t)NROWS * NCOLS];
__device__ __align__(256) __half g_bh[(size_t)NCOLS * KDIM];   // support^T (fp16)

// -------- helpers --------
__device__ __forceinline__ uint32_t smem_u32(const void* p) {
    uint32_t a;
    asm("{ .reg .u64 t; cvta.to.shared.u64 t, %1; cvt.u32.u64 %0, t; }" : "=r"(a) : "l"(p));
    return a;
}
__device__ __forceinline__ uint32_t sw128(uint32_t off) { return off ^ ((off >> 3) & 0x70); }

__device__ __forceinline__ uint32_t pack2h(float a, float b) {   // a -> LOW half
    uint32_t r;
    asm("cvt.rn.f16x2.f32 %0, %1, %2;" : "=r"(r) : "f"(b), "f"(a));
    return r;
}
__device__ __forceinline__ void sts128(uint32_t addr, uint32_t a, uint32_t b, uint32_t c, uint32_t d) {
    asm volatile("st.shared.v4.b32 [%0], {%1,%2,%3,%4};"
                 :: "r"(addr), "r"(a), "r"(b), "r"(c), "r"(d) : "memory");
}
__device__ __forceinline__ void lds128f(uint32_t addr, float* v) {
    asm volatile("ld.shared.v4.f32 {%0,%1,%2,%3}, [%4];"
                 : "=f"(v[0]), "=f"(v[1]), "=f"(v[2]), "=f"(v[3]) : "r"(addr));
}
__device__ __forceinline__ void cp_async16(uint32_t saddr, const void* gaddr) {
    asm volatile("cp.async.cg.shared.global [%0], [%1], 16;"
                 :: "r"(saddr), "l"(gaddr) : "memory");
}
#define CP_COMMIT() asm volatile("cp.async.commit_group;" ::: "memory")
#define CP_WAIT1()  asm volatile("cp.async.wait_group 1;" ::: "memory")
#define CP_WAIT0()  asm volatile("cp.async.wait_group 0;" ::: "memory")

#define LDSM4(r, addr) \
    asm volatile("ldmatrix.sync.aligned.m8n8.x4.shared.b16 {%0,%1,%2,%3}, [%4];" \
                 : "=r"((r)[0]), "=r"((r)[1]), "=r"((r)[2]), "=r"((r)[3]) : "r"(addr))

#define MMAH(d, a, b0_, b1_) \
    asm volatile("mma.sync.aligned.m16n8k16.row.col.f32.f16.f16.f32 " \
                 "{%0,%1,%2,%3}, {%4,%5,%6,%7}, {%8,%9}, {%0,%1,%2,%3};" \
                 : "+f"((d)[0]), "+f"((d)[1]), "+f"((d)[2]), "+f"((d)[3]) \
                 : "r"((a)[0]), "r"((a)[1]), "r"((a)[2]), "r"((a)[3]), \
                   "r"(b0_), "r"(b1_))

// -------- prep: support = x @ W ; store fp32 + fp16 transposed plane --------
__global__ __launch_bounds__(256) void gcn_prep(const float* __restrict__ x,
                                                const float* __restrict__ W) {
    int tid = threadIdx.x;
    int rg = tid >> 3, cg = tid & 7;
    int row0 = blockIdx.x * 128 + rg * 4;   // k dim of support^T
    int c0 = cg * 8;                        // n dim
    float acc[4][8];
#pragma unroll
    for (int i = 0; i < 4; i++)
#pragma unroll
        for (int j = 0; j < 8; j++) acc[i][j] = 0.f;

    const float4* x4 = reinterpret_cast<const float4*>(x);
    const float4* W4 = reinterpret_cast<const float4*>(W);

    for (int k4 = 0; k4 < 64; k4++) {
        float4 xv[4];
#pragma unroll
        for (int i = 0; i < 4; i++) xv[i] = __ldg(&x4[(size_t)(row0 + i) * 64 + k4]);
#pragma unroll
        for (int j = 0; j < 4; j++) {
            float4 wa = __ldg(&W4[(k4 * 4 + j) * 16 + cg * 2]);
            float4 wb = __ldg(&W4[(k4 * 4 + j) * 16 + cg * 2 + 1]);
#pragma unroll
            for (int i = 0; i < 4; i++) {
                float xs = (j == 0) ? xv[i].x : (j == 1) ? xv[i].y : (j == 2) ? xv[i].z : xv[i].w;
                acc[i][0] = fmaf(xs, wa.x, acc[i][0]);
                acc[i][1] = fmaf(xs, wa.y, acc[i][1]);
                acc[i][2] = fmaf(xs, wa.z, acc[i][2]);
                acc[i][3] = fmaf(xs, wa.w, acc[i][3]);
                acc[i][4] = fmaf(xs, wb.x, acc[i][4]);
                acc[i][5] = fmaf(xs, wb.y, acc[i][5]);
                acc[i][6] = fmaf(xs, wb.z, acc[i][6]);
                acc[i][7] = fmaf(xs, wb.w, acc[i][7]);
            }
        }
    }
#pragma unroll
    for (int i = 0; i < 4; i++) {
        float* sp = g_sup + (size_t)(row0 + i) * NCOLS + c0;
        reinterpret_cast<float4*>(sp)[0] = make_float4(acc[i][0], acc[i][1], acc[i][2], acc[i][3]);
        reinterpret_cast<float4*>(sp)[1] = make_float4(acc[i][4], acc[i][5], acc[i][6], acc[i][7]);
    }
#pragma unroll
    for (int j = 0; j < 8; j++) {
        int n = c0 + j;
        uint32_t hv0 = pack2h(acc[0][j], acc[1][j]);
        uint32_t hv1 = pack2h(acc[2][j], acc[3][j]);
        *reinterpret_cast<uint2*>(g_bh + (size_t)n * KDIM + row0) = make_uint2(hv0, hv1);
    }
}

// -------- main: out = relu(adj @ support + support + b) --------
// 256 CTAs x 64 rows, 256 threads, 2 CTAs/SM. Warp grid 2m x 2n x 2k; tile 32x32 on K/2.
// A: 2-stage smem + distance-2 reg ring. B: 4-stage smem via cp.async.cg (distance 2).
#define A_STAGE  8192
#define B_BASE   16384
#define B_STAGE  8192
#define SMEM_MAIN (1024 + 2 * A_STAGE + 4 * B_STAGE)

__device__ __forceinline__ void stage_A(uint32_t At, const float* f,
                                        uint32_t s0, uint32_t s1) {
    uint32_t h[8];
#pragma unroll
    for (int q = 0; q < 8; q++) h[q] = pack2h(f[2 * q], f[2 * q + 1]);
    sts128(At + s0, h[0], h[1], h[2], h[3]);
    sts128(At + s1, h[4], h[5], h[6], h[7]);
}

__global__ __launch_bounds__(256, 2) void gcn_main(const float* __restrict__ adj,
                                                   const float* __restrict__ bias,
                                                   float* __restrict__ out) {
    extern __shared__ char dsm[];
    uint32_t tiles = (smem_u32(dsm) + 1023) & ~1023u;
    int tid = threadIdx.x;
    int wid = tid >> 5;
    int lane = tid & 31;
    int row0 = blockIdx.x * 64;
    int wm = wid & 1, wn = (wid >> 1) & 1, wk = wid >> 2;

    // A loader: 64 rows x 4 segs of 16 floats -> 32B fp16
    int arow = tid >> 2, aseg = tid & 3;
    uint32_t a_s0 = sw128((uint32_t)arow * 128 + (uint32_t)aseg * 32);
    uint32_t a_s1 = sw128((uint32_t)arow * 128 + (uint32_t)aseg * 32 + 16);
    const float4* apbase = reinterpret_cast<const float4*>(
        adj + (size_t)(row0 + arow) * KDIM + aseg * 16);

    // B loader: 64 rows x 4 segs of 32B via cp.async (2x16B per thread)
    int bn = tid >> 2, bq = tid & 3;
    const uint4* bpbase = reinterpret_cast<const uint4*>(
        reinterpret_cast<const char*>(g_bh) + ((size_t)bn * KDIM) * 2 + (size_t)bq * 32);
    uint32_t b_s0 = sw128((uint32_t)bn * 128 + (uint32_t)bq * 32);
    uint32_t b_s1 = sw128((uint32_t)bn * 128 + (uint32_t)bq * 32 + 16);

    uint32_t Ast[2], Bst[4];
    Ast[0] = tiles;           Ast[1] = tiles + A_STAGE;
#pragma unroll
    for (int s = 0; s < 4; s++) Bst[s] = tiles + B_BASE + (uint32_t)s * B_STAGE;

#define CP_B(Bt, c) do { \
    const uint4* _s = bpbase + (size_t)(c) * BSTRIDE; \
    cp_async16((Bt) + b_s0, _s); \
    cp_async16((Bt) + b_s1, _s + 1); \
    CP_COMMIT(); \
} while (0)

    // fragment lane mappings
    uint32_t a_r = ((lane >> 3) & 1) * 8 + (lane & 7);
    uint32_t a_k = ((lane >> 4) & 1) * 16;
    uint32_t b_n = ((lane >> 4) & 1) * 8 + (lane & 7);
    uint32_t b_k = ((lane >> 3) & 1) * 16;
    uint32_t arowb[2], browb[2];
#pragma unroll
    for (int mt = 0; mt < 2; mt++) arowb[mt] = (wm * 32 + mt * 16 + a_r) * 128;
#pragma unroll
    for (int p = 0; p < 2; p++)   browb[p]  = (wn * 32 + p * 16 + b_n) * 128;

    float acc[2][4][4];
#pragma unroll
    for (int mt = 0; mt < 2; mt++)
#pragma unroll
        for (int nt = 0; nt < 4; nt++)
#pragma unroll
            for (int j = 0; j < 4; j++) acc[mt][nt][j] = 0.f;

#define MMA_CHUNK(At, Bt) do { \
    _Pragma("unroll") \
    for (int ks = 0; ks < 2; ks++) { \
        uint32_t ko = (uint32_t)wk * 64 + (uint32_t)(ks * 32); \
        uint32_t af[2][4], bf[2][4]; \
        _Pragma("unroll") \
        for (int mt = 0; mt < 2; mt++) \
            LDSM4(af[mt], (At) + sw128(arowb[mt] + ko + a_k)); \
        _Pragma("unroll") \
        for (int p = 0; p < 2; p++) \
            LDSM4(bf[p], (Bt) + sw128(browb[p] + ko + b_k)); \
        _Pragma("unroll") \
        for (int mt = 0; mt < 2; mt++) { \
            _Pragma("unroll") \
            for (int nt = 0; nt < 4; nt++) { \
                int p = nt >> 1, h = (nt & 1) * 2; \
                MMAH(acc[mt][nt], af[mt], bf[p][h], bf[p][h + 1]); \
            } \
        } \
    } \
} while (0)

    float av[2][16];

    // ---- prologue: B(0)->st0, B(1)->st1 async; A(0) staged; A(1) in regs ----
    {
        CP_B(Bst[0], 0);
        CP_B(Bst[1], 1);
#pragma unroll
        for (int q = 0; q < 4; q++)
            reinterpret_cast<float4*>(av[0])[q] = __ldcs(&apbase[q]);
        stage_A(Ast[0], av[0], a_s0, a_s1);
#pragma unroll
        for (int q = 0; q < 4; q++)
            reinterpret_cast<float4*>(av[1])[q] = __ldcs(&apbase[(size_t)(KC / 4) + q]);
        CP_WAIT1();   // B(0) done, B(1) may fly
    }
    __syncthreads();

    // ---- main loop: unroll x4; chunk c+h reads A stage (h&1), B stage h ----
#pragma unroll 1
    for (int c = 0; c < NCHUNK; c += 4) {
#define HALF(hh) do { \
        constexpr int h = (hh); \
        const bool ld_ok = (c + h + 2 < NCHUNK); \
        if (ld_ok) { \
            CP_B(Bst[(h + 2) & 3], c + h + 2); \
            const float4* ap = apbase + (size_t)(c + h + 2) * (KC / 4); \
            _Pragma("unroll") \
            for (int q = 0; q < 4; q++) \
                reinterpret_cast<float4*>(av[h & 1])[q] = __ldcs(&ap[q]); \
        } \
        MMA_CHUNK(Ast[h & 1], Bst[h]); \
        if (c + h + 1 < NCHUNK) \
            stage_A(Ast[(h + 1) & 1], av[(h + 1) & 1], a_s0, a_s1); \
        if (ld_ok) { CP_WAIT1(); } else { CP_WAIT0(); } \
        __syncthreads(); \
    } while (0)

        HALF(0);
        HALF(1);
        HALF(2);
        HALF(3);
#undef HALF
    }
#undef MMA_CHUNK
#undef CP_B

    // ---- merge k-split partials: wk=1 warps dump accs to smem ----
    if (wk == 1) {
#pragma unroll
        for (int mt = 0; mt < 2; mt++)
#pragma unroll
            for (int nt = 0; nt < 4; nt++) {
                uint32_t off = tiles + (uint32_t)(wid & 3) * 4096 +
                               (uint32_t)(mt * 4 + nt) * 512 + (uint32_t)lane * 16;
                sts128(off, __float_as_uint(acc[mt][nt][0]), __float_as_uint(acc[mt][nt][1]),
                             __float_as_uint(acc[mt][nt][2]), __float_as_uint(acc[mt][nt][3]));
            }
    }
    __syncthreads();

    // ---- epilogue (wk=0 warps): out = relu(acc + partial + support + bias) ----
    if (wk == 0) {
        int g = lane >> 2, t = lane & 3;
#pragma unroll
        for (int mt = 0; mt < 2; mt++) {
            int ra = row0 + wm * 32 + mt * 16 + g;
#pragma unroll
            for (int nt = 0; nt < 4; nt++) {
                float p[4];
                lds128f(tiles + (uint32_t)wid * 4096 + (uint32_t)(mt * 4 + nt) * 512 +
                        (uint32_t)lane * 16, p);
                int col = wn * 32 + nt * 8 + t * 2;
                float2 bb = *reinterpret_cast<const float2*>(bias + col);
                float2 s0 = *reinterpret_cast<const float2*>(g_sup + (size_t)ra * NCOLS + col);
                float2 s1 = *reinterpret_cast<const float2*>(g_sup + (size_t)(ra + 8) * NCOLS + col);
                float2 r0, r1;
                r0.x = fmaxf(acc[mt][nt][0] + p[0] + s0.x + bb.x, 0.f);
                r0.y = fmaxf(acc[mt][nt][1] + p[1] + s0.y + bb.y, 0.f);
                r1.x = fmaxf(acc[mt][nt][2] + p[2] + s1.x + bb.x, 0.f);
                r1.y = fmaxf(acc[mt][nt][3] + p[3] + s1.y + bb.y, 0.f);
                *reinterpret_cast<float2*>(out + (size_t)ra * NCOLS + col) = r0;
                *reinterpret_cast<float2*>(out + (size_t)(ra + 8) * NCOLS + col) = r1;
            }
        }
    }
}

extern "C" void kernel_launch(void* const* d_in, const int* in_sizes, int n_in,
                              void* d_out, int out_size) {
    const float *x = nullptr, *adj = nullptr, *W = nullptr, *b = nullptr;
    for (int i = 0; i < n_in; i++) {
        long s = in_sizes[i];
        if (s == (long)NROWS * 256)        x   = (const float*)d_in[i];
        else if (s == (long)NROWS * NROWS) adj = (const float*)d_in[i];
        else if (s == 256L * NCOLS)        W   = (const float*)d_in[i];
        else if (s == (long)NCOLS)         b   = (const float*)d_in[i];
    }
    cudaFuncSetAttribute(gcn_main, cudaFuncAttributeMaxDynamicSharedMemorySize, SMEM_MAIN);
    gcn_prep<<<128, 256>>>(x, W);
    gcn_main<<<256, 256, SMEM_MAIN>>>(adj, b, (float*)d_out);
}

// round 15
// speedup vs baseline: 1.2026x; 1.0633x over previous
#include <cuda_runtime.h>
#include <cuda_fp16.h>
#include <cstdint>

#define NROWS 16384
#define KDIM  16384
#define NCOLS 64
#define KC    64
#define NCHUNK (KDIM / KC)
#define BSTRIDE ((KC * 2) / 16)   // uint4s per chunk of one B row = 8

// -------- device scratch --------
__device__ __align__(256) float  g_sup[(size_t)NROWS * NCOLS];
__device__ __align__(256) __half g_bh[(size_t)NCOLS * KDIM];   // support^T (fp16)

// -------- helpers --------
__device__ __forceinline__ uint32_t smem_u32(const void* p) {
    uint32_t a;
    asm("{ .reg .u64 t; cvta.to.shared.u64 t, %1; cvt.u32.u64 %0, t; }" : "=r"(a) : "l"(p));
    return a;
}
__device__ __forceinline__ uint32_t sw128(uint32_t off) { return off ^ ((off >> 3) & 0x70); }

__device__ __forceinline__ uint32_t pack2h(float a, float b) {   // a -> LOW half
    uint32_t r;
    asm("cvt.rn.f16x2.f32 %0, %1, %2;" : "=r"(r) : "f"(b), "f"(a));
    return r;
}
__device__ __forceinline__ void sts128(uint32_t addr, uint32_t a, uint32_t b, uint32_t c, uint32_t d) {
    asm volatile("st.shared.v4.b32 [%0], {%1,%2,%3,%4};"
                 :: "r"(addr), "r"(a), "r"(b), "r"(c), "r"(d) : "memory");
}
__device__ __forceinline__ void lds128f(uint32_t addr, float* v) {
    asm volatile("ld.shared.v4.f32 {%0,%1,%2,%3}, [%4];"
                 : "=f"(v[0]), "=f"(v[1]), "=f"(v[2]), "=f"(v[3]) : "r"(addr));
}
__device__ __forceinline__ void cp_async16(uint32_t saddr, const void* gaddr) {
    asm volatile("cp.async.cg.shared.global [%0], [%1], 16;"
                 :: "r"(saddr), "l"(gaddr) : "memory");
}
#define CP_COMMIT() asm volatile("cp.async.commit_group;" ::: "memory")
#define CP_WAIT1()  asm volatile("cp.async.wait_group 1;" ::: "memory")
#define CP_WAIT0()  asm volatile("cp.async.wait_group 0;" ::: "memory")

#define LDSM4(r, addr) \
    asm volatile("ldmatrix.sync.aligned.m8n8.x4.shared.b16 {%0,%1,%2,%3}, [%4];" \
                 : "=r"((r)[0]), "=r"((r)[1]), "=r"((r)[2]), "=r"((r)[3]) : "r"(addr))

#define MMAH(d, a, b0_, b1_) \
    asm volatile("mma.sync.aligned.m16n8k16.row.col.f32.f16.f16.f32 " \
                 "{%0,%1,%2,%3}, {%4,%5,%6,%7}, {%8,%9}, {%0,%1,%2,%3};" \
                 : "+f"((d)[0]), "+f"((d)[1]), "+f"((d)[2]), "+f"((d)[3]) \
                 : "r"((a)[0]), "r"((a)[1]), "r"((a)[2]), "r"((a)[3]), \
                   "r"(b0_), "r"(b1_))

// -------- prep: support = x @ W (smem-tiled) ; store fp32 + fp16 transposed plane --------
// 128 CTAs x 128 rows, 256 threads. smem: x tile 128x64 fp32 (pitch 65) + W tile 64x64 fp32.
#define XS_PITCH 65
#define PREP_SMEM ((128 * XS_PITCH + 64 * 64) * 4)

__global__ __launch_bounds__(256) void gcn_prep(const float* __restrict__ x,
                                                const float* __restrict__ W) {
    extern __shared__ float psm[];
    float* xs = psm;                       // [128][65]
    float* ws = psm + 128 * XS_PITCH;      // [64][64]

    int tid = threadIdx.x;
    int rg = tid >> 3, cg = tid & 7;       // same mapping as before (write-out unchanged)
    int row0 = blockIdx.x * 128 + rg * 4;  // k dim of support^T
    int c0 = cg * 8;                       // n dim
    float acc[4][8];
#pragma unroll
    for (int i = 0; i < 4; i++)
#pragma unroll
        for (int j = 0; j < 8; j++) acc[i][j] = 0.f;

    const float4* x4 = reinterpret_cast<const float4*>(x);   // row pitch 64 float4
    const float4* W4 = reinterpret_cast<const float4*>(W);   // row pitch 16 float4

    for (int kt = 0; kt < 4; kt++) {
        // stage x tile: 128 rows x 16 float4, fully coalesced (16 thr x 16B runs)
#pragma unroll
        for (int i = 0; i < 8; i++) {
            int lin = tid + i * 256;           // 0..2047
            int r = lin >> 4, c4 = lin & 15;
            float4 v = __ldg(&x4[(size_t)(blockIdx.x * 128 + r) * 64 + kt * 16 + c4]);
            float* dst = xs + r * XS_PITCH + c4 * 4;
            dst[0] = v.x; dst[1] = v.y; dst[2] = v.z; dst[3] = v.w;
        }
        // stage W tile: 64 rows x 16 float4
#pragma unroll
        for (int i = 0; i < 4; i++) {
            int lin = tid + i * 256;           // 0..1023
            int r = lin >> 4, c4 = lin & 15;
            float4 v = __ldg(&W4[(size_t)(kt * 64 + r) * 16 + c4]);
            reinterpret_cast<float4*>(ws)[r * 16 + c4] = v;
        }
        __syncthreads();

        // compute: 4 rows x 8 cols per thread
        const float* xrow0 = xs + (rg * 4 + 0) * XS_PITCH;
        const float* xrow1 = xs + (rg * 4 + 1) * XS_PITCH;
        const float* xrow2 = xs + (rg * 4 + 2) * XS_PITCH;
        const float* xrow3 = xs + (rg * 4 + 3) * XS_PITCH;
#pragma unroll 4
        for (int kk = 0; kk < 64; kk++) {
            float a0 = xrow0[kk], a1 = xrow1[kk], a2 = xrow2[kk], a3 = xrow3[kk];
            float4 wa = reinterpret_cast<const float4*>(ws)[kk * 16 + cg * 2];
            float4 wb = reinterpret_cast<const float4*>(ws)[kk * 16 + cg * 2 + 1];
            float av_[4] = {a0, a1, a2, a3};
#pragma unroll
            for (int i = 0; i < 4; i++) {
                acc[i][0] = fmaf(av_[i], wa.x, acc[i][0]);
                acc[i][1] = fmaf(av_[i], wa.y, acc[i][1]);
                acc[i][2] = fmaf(av_[i], wa.z, acc[i][2]);
                acc[i][3] = fmaf(av_[i], wa.w, acc[i][3]);
                acc[i][4] = fmaf(av_[i], wb.x, acc[i][4]);
                acc[i][5] = fmaf(av_[i], wb.y, acc[i][5]);
                acc[i][6] = fmaf(av_[i], wb.z, acc[i][6]);
                acc[i][7] = fmaf(av_[i], wb.w, acc[i][7]);
            }
        }
        __syncthreads();
    }

    // write-out (identical layout to previous prep)
#pragma unroll
    for (int i = 0; i < 4; i++) {
        float* sp = g_sup + (size_t)(row0 + i) * NCOLS + c0;
        reinterpret_cast<float4*>(sp)[0] = make_float4(acc[i][0], acc[i][1], acc[i][2], acc[i][3]);
        reinterpret_cast<float4*>(sp)[1] = make_float4(acc[i][4], acc[i][5], acc[i][6], acc[i][7]);
    }
#pragma unroll
    for (int j = 0; j < 8; j++) {
        int n = c0 + j;
        uint32_t hv0 = pack2h(acc[0][j], acc[1][j]);
        uint32_t hv1 = pack2h(acc[2][j], acc[3][j]);
        *reinterpret_cast<uint2*>(g_bh + (size_t)n * KDIM + row0) = make_uint2(hv0, hv1);
    }
}

// -------- main: out = relu(adj @ support + support + b) --------
// 256 CTAs x 64 rows, 256 threads, 2 CTAs/SM. Warp grid 2m x 2n x 2k; tile 32x32 on K/2.
// A: 2-stage smem + distance-2 reg ring. B: 4-stage smem via cp.async.cg (distance 2).
#define A_STAGE  8192
#define B_BASE   16384
#define B_STAGE  8192
#define SMEM_MAIN (1024 + 2 * A_STAGE + 4 * B_STAGE)

__device__ __forceinline__ void stage_A(uint32_t At, const float* f,
                                        uint32_t s0, uint32_t s1) {
    uint32_t h[8];
#pragma unroll
    for (int q = 0; q < 8; q++) h[q] = pack2h(f[2 * q], f[2 * q + 1]);
    sts128(At + s0, h[0], h[1], h[2], h[3]);
    sts128(At + s1, h[4], h[5], h[6], h[7]);
}

__global__ __launch_bounds__(256, 2) void gcn_main(const float* __restrict__ adj,
                                                   const float* __restrict__ bias,
                                                   float* __restrict__ out) {
    extern __shared__ char dsm[];
    uint32_t tiles = (smem_u32(dsm) + 1023) & ~1023u;
    int tid = threadIdx.x;
    int wid = tid >> 5;
    int lane = tid & 31;
    int row0 = blockIdx.x * 64;
    int wm = wid & 1, wn = (wid >> 1) & 1, wk = wid >> 2;

    // A loader: 64 rows x 4 segs of 16 floats -> 32B fp16
    int arow = tid >> 2, aseg = tid & 3;
    uint32_t a_s0 = sw128((uint32_t)arow * 128 + (uint32_t)aseg * 32);
    uint32_t a_s1 = sw128((uint32_t)arow * 128 + (uint32_t)aseg * 32 + 16);
    const float4* apbase = reinterpret_cast<const float4*>(
        adj + (size_t)(row0 + arow) * KDIM + aseg * 16);

    // B loader: 64 rows x 4 segs of 32B via cp.async (2x16B per thread)
    int bn = tid >> 2, bq = tid & 3;
    const uint4* bpbase = reinterpret_cast<const uint4*>(
        reinterpret_cast<const char*>(g_bh) + ((size_t)bn * KDIM) * 2 + (size_t)bq * 32);
    uint32_t b_s0 = sw128((uint32_t)bn * 128 + (uint32_t)bq * 32);
    uint32_t b_s1 = sw128((uint32_t)bn * 128 + (uint32_t)bq * 32 + 16);

    uint32_t Ast[2], Bst[4];
    Ast[0] = tiles;           Ast[1] = tiles + A_STAGE;
#pragma unroll
    for (int s = 0; s < 4; s++) Bst[s] = tiles + B_BASE + (uint32_t)s * B_STAGE;

#define CP_B(Bt, c) do { \
    const uint4* _s = bpbase + (size_t)(c) * BSTRIDE; \
    cp_async16((Bt) + b_s0, _s); \
    cp_async16((Bt) + b_s1, _s + 1); \
    CP_COMMIT(); \
} while (0)

    // fragment lane mappings
    uint32_t a_r = ((lane >> 3) & 1) * 8 + (lane & 7);
    uint32_t a_k = ((lane >> 4) & 1) * 16;
    uint32_t b_n = ((lane >> 4) & 1) * 8 + (lane & 7);
    uint32_t b_k = ((lane >> 3) & 1) * 16;
    uint32_t arowb[2], browb[2];
#pragma unroll
    for (int mt = 0; mt < 2; mt++) arowb[mt] = (wm * 32 + mt * 16 + a_r) * 128;
#pragma unroll
    for (int p = 0; p < 2; p++)   browb[p]  = (wn * 32 + p * 16 + b_n) * 128;

    float acc[2][4][4];
#pragma unroll
    for (int mt = 0; mt < 2; mt++)
#pragma unroll
        for (int nt = 0; nt < 4; nt++)
#pragma unroll
            for (int j = 0; j < 4; j++) acc[mt][nt][j] = 0.f;

#define MMA_CHUNK(At, Bt) do { \
    _Pragma("unroll") \
    for (int ks = 0; ks < 2; ks++) { \
        uint32_t ko = (uint32_t)wk * 64 + (uint32_t)(ks * 32); \
        uint32_t af[2][4], bf[2][4]; \
        _Pragma("unroll") \
        for (int mt = 0; mt < 2; mt++) \
            LDSM4(af[mt], (At) + sw128(arowb[mt] + ko + a_k)); \
        _Pragma("unroll") \
        for (int p = 0; p < 2; p++) \
            LDSM4(bf[p], (Bt) + sw128(browb[p] + ko + b_k)); \
        _Pragma("unroll") \
        for (int mt = 0; mt < 2; mt++) { \
            _Pragma("unroll") \
            for (int nt = 0; nt < 4; nt++) { \
                int p = nt >> 1, h = (nt & 1) * 2; \
                MMAH(acc[mt][nt], af[mt], bf[p][h], bf[p][h + 1]); \
            } \
        } \
    } \
} while (0)

    float av[2][16];

    // ---- prologue: B(0)->st0, B(1)->st1 async; A(0) staged; A(1) in regs ----
    {
        CP_B(Bst[0], 0);
        CP_B(Bst[1], 1);
#pragma unroll
        for (int q = 0; q < 4; q++)
            reinterpret_cast<float4*>(av[0])[q] = __ldcs(&apbase[q]);
        stage_A(Ast[0], av[0], a_s0, a_s1);
#pragma unroll
        for (int q = 0; q < 4; q++)
            reinterpret_cast<float4*>(av[1])[q] = __ldcs(&apbase[(size_t)(KC / 4) + q]);
        CP_WAIT1();   // B(0) done, B(1) may fly
    }
    __syncthreads();

    // ---- main loop: unroll x4; chunk c+h reads A stage (h&1), B stage h ----
#pragma unroll 1
    for (int c = 0; c < NCHUNK; c += 4) {
#define HALF(hh) do { \
        constexpr int h = (hh); \
        const bool ld_ok = (c + h + 2 < NCHUNK); \
        if (ld_ok) { \
            CP_B(Bst[(h + 2) & 3], c + h + 2); \
            const float4* ap = apbase + (size_t)(c + h + 2) * (KC / 4); \
            _Pragma("unroll") \
            for (int q = 0; q < 4; q++) \
                reinterpret_cast<float4*>(av[h & 1])[q] = __ldcs(&ap[q]); \
        } \
        MMA_CHUNK(Ast[h & 1], Bst[h]); \
        if (c + h + 1 < NCHUNK) \
            stage_A(Ast[(h + 1) & 1], av[(h + 1) & 1], a_s0, a_s1); \
        if (ld_ok) { CP_WAIT1(); } else { CP_WAIT0(); } \
        __syncthreads(); \
    } while (0)

        HALF(0);
        HALF(1);
        HALF(2);
        HALF(3);
#undef HALF
    }
#undef MMA_CHUNK
#undef CP_B

    // ---- merge k-split partials: wk=1 warps dump accs to smem ----
    if (wk == 1) {
#pragma unroll
        for (int mt = 0; mt < 2; mt++)
#pragma unroll
            for (int nt = 0; nt < 4; nt++) {
                uint32_t off = tiles + (uint32_t)(wid & 3) * 4096 +
                               (uint32_t)(mt * 4 + nt) * 512 + (uint32_t)lane * 16;
                sts128(off, __float_as_uint(acc[mt][nt][0]), __float_as_uint(acc[mt][nt][1]),
                             __float_as_uint(acc[mt][nt][2]), __float_as_uint(acc[mt][nt][3]));
            }
    }
    __syncthreads();

    // ---- epilogue (wk=0 warps): out = relu(acc + partial + support + bias) ----
    if (wk == 0) {
        int g = lane >> 2, t = lane & 3;
#pragma unroll
        for (int mt = 0; mt < 2; mt++) {
            int ra = row0 + wm * 32 + mt * 16 + g;
#pragma unroll
            for (int nt = 0; nt < 4; nt++) {
                float p[4];
                lds128f(tiles + (uint32_t)wid * 4096 + (uint32_t)(mt * 4 + nt) * 512 +
                        (uint32_t)lane * 16, p);
                int col = wn * 32 + nt * 8 + t * 2;
                float2 bb = *reinterpret_cast<const float2*>(bias + col);
                float2 s0 = *reinterpret_cast<const float2*>(g_sup + (size_t)ra * NCOLS + col);
                float2 s1 = *reinterpret_cast<const float2*>(g_sup + (size_t)(ra + 8) * NCOLS + col);
                float2 r0, r1;
                r0.x = fmaxf(acc[mt][nt][0] + p[0] + s0.x + bb.x, 0.f);
                r0.y = fmaxf(acc[mt][nt][1] + p[1] + s0.y + bb.y, 0.f);
                r1.x = fmaxf(acc[mt][nt][2] + p[2] + s1.x + bb.x, 0.f);
                r1.y = fmaxf(acc[mt][nt][3] + p[3] + s1.y + bb.y, 0.f);
                *reinterpret_cast<float2*>(out + (size_t)ra * NCOLS + col) = r0;
                *reinterpret_cast<float2*>(out + (size_t)(ra + 8) * NCOLS + col) = r1;
            }
        }
    }
}

extern "C" void kernel_launch(void* const* d_in, const int* in_sizes, int n_in,
                              void* d_out, int out_size) {
    const float *x = nullptr, *adj = nullptr, *W = nullptr, *b = nullptr;
    for (int i = 0; i < n_in; i++) {
        long s = in_sizes[i];
        if (s == (long)NROWS * 256)        x   = (const float*)d_in[i];
        else if (s == (long)NROWS * NROWS) adj = (const float*)d_in[i];
        else if (s == 256L * NCOLS)        W   = (const float*)d_in[i];
        else if (s == (long)NCOLS)         b   = (const float*)d_in[i];
    }
    cudaFuncSetAttribute(gcn_prep, cudaFuncAttributeMaxDynamicSharedMemorySize, PREP_SMEM);
    cudaFuncSetAttribute(gcn_main, cudaFuncAttributeMaxDynamicSharedMemorySize, SMEM_MAIN);
    gcn_prep<<<128, 256, PREP_SMEM>>>(x, W);
    gcn_main<<<256, 256, SMEM_MAIN>>>(adj, b, (float*)d_out);
}